// round 8
// baseline (speedup 1.0000x reference)
#include <cuda_runtime.h>
#include <math.h>

#define SS 1024
#define CC 4096
#define KK 4
#define NB 128          // blocks (NB * 8 warps == SS rows); NB <= SM count -> co-resident

// ---------------- scratch (no allocations allowed) ----------------
__device__ float g_sums[8 * SS];   // linear dots  sum_j exp(logPi[c_k][j]) * recip[s][j]
__device__ float g_P[9 * SS];      // exp(logPi) rows: 0..3 = c1 splits, 4..7 = c2 splits, 8 = root
__device__ float g_invcnt[SS];     // 1 / cnt[s]
__device__ float g_En[SS];         // E_new[s]  (linear)
__device__ float g_ps[NB];         // per-block partial sums of lin[s]
__device__ unsigned int g_bar1 = 0, g_bar2 = 0;   // monotonic ticket counters (never reset)

__device__ __forceinline__ float softplusf(float x) {
    if (x > 20.0f)  return x;
    if (x < -20.0f) return expf(x);
    return log1pf(expf(x));
}

// Grid barrier: monotonic counter, replay-safe (no reset), wrap-safe compare.
// All NB blocks are co-resident (NB <= 148 SMs), so spin cannot deadlock.
__device__ __forceinline__ void grid_barrier(unsigned int* bar) {
    __threadfence();                       // release
    __syncthreads();
    if (threadIdx.x == 0) {
        unsigned int t = atomicAdd(bar, 1u);
        unsigned int target = (t / NB + 1u) * NB;
        while ((int)(*(volatile unsigned int*)bar - target) < 0) { }
    }
    __syncthreads();
    __threadfence();                       // acquire
}

__global__ void __launch_bounds__(256) k_fused(
    const float* __restrict__ log_delta,
    const float* __restrict__ log_tau,
    const float* __restrict__ log_lambda,
    const float* __restrict__ E,
    const float* __restrict__ logPi,
    const int*   __restrict__ sC1,
    const int*   __restrict__ sC2,
    const float* __restrict__ recip,
    const int*   __restrict__ splits_c1,
    const int*   __restrict__ splits_c2,
    const float* __restrict__ log_q,
    const void*  __restrict__ is_leaf,
    const int*   __restrict__ rootp,
    float*       __restrict__ out)
{
    __shared__ float sw[8 * SS];   // exp(logPi[c_k][j])  (32 KB)
    __shared__ float sE[SS];       // E (4 KB)
    __shared__ float s_part[8];    // per-warp epilogue partials

    const int tid  = threadIdx.x;
    const int b    = blockIdx.x;
    const int warp = tid >> 5, lane = tid & 31;

    // ---- issue ALL recip loads first: 8 outstanding LDG.128 per warp.
    //      These have no smem dependence, so their DRAM latency overlaps
    //      with the exp-staging phase below.
    const int s = b * 8 + warp;
    const float4* rrow = (const float4*)(recip + (size_t)s * SS);
    float4 rv[8];
    #pragma unroll
    for (int it = 0; it < 8; it++) rv[it] = rrow[lane + it * 32];

    // ---- scalar constants (uniform, L2-hot broadcasts) ----
    const int root = rootp[0];
    const float delta = softplusf(log_delta[0]);
    const float tau   = softplusf(log_tau[0]);
    const float lam   = softplusf(log_lambda[0]);
    const float rs = 1.0f + delta + tau + lam;
    const float pS = 1.0f / rs, pD = delta / rs, pT = tau / rs, pL = lam / rs;

    // ---- stage weights + E in shared ----
    #pragma unroll
    for (int k = 0; k < 8; k++) {
        int c = (k < 4) ? splits_c1[root * KK + k] : splits_c2[root * KK + (k - 4)];
        float4 v = ((const float4*)(logPi + (size_t)c * SS))[tid];
        float4 w;
        w.x = expf(v.x); w.y = expf(v.y); w.z = expf(v.z); w.w = expf(v.w);
        ((float4*)(sw + k * SS))[tid] = w;
    }
    ((float4*)sE)[tid] = ((const float4*)E)[tid];

    // blocks 0..7 publish exp'd split rows; block 8 publishes exp'd root row
    if (b < 8) {
        float4 w = ((const float4*)(sw + b * SS))[tid];   // own thread's write
        ((float4*)(g_P + b * SS))[tid] = w;
    } else if (b == 8) {
        float4 v = ((const float4*)(logPi + (size_t)root * SS))[tid];
        float4 w;
        w.x = expf(v.x); w.y = expf(v.y); w.z = expf(v.z); w.w = expf(v.w);
        ((float4*)(g_P + 8 * SS))[tid] = w;
    }
    __syncthreads();

    // ---- row phase compute: all rv already in registers ----
    {
        float acc[10];
        #pragma unroll
        for (int q = 0; q < 10; q++) acc[q] = 0.0f;

        #pragma unroll
        for (int it = 0; it < 8; it++) {
            const int j4 = lane + it * 32;
            const float4 r = rv[it];
            const float4 ev = ((const float4*)sE)[j4];
            acc[0] += r.x + r.y + r.z + r.w;
            acc[1] += r.x * ev.x + r.y * ev.y + r.z * ev.z + r.w * ev.w;
            #pragma unroll
            for (int k = 0; k < 8; k++) {
                const float4 wv = ((const float4*)(sw + k * SS))[j4];
                acc[2 + k] += r.x * wv.x + r.y * wv.y + r.z * wv.z + r.w * wv.w;
            }
        }

        #pragma unroll
        for (int q = 0; q < 10; q++)
            #pragma unroll
            for (int o = 16; o > 0; o >>= 1)
                acc[q] += __shfl_xor_sync(0xffffffffu, acc[q], o);

        if (lane == 0) {
            float cnt = fmaxf(acc[0], 1.0f);
            float inv = 1.0f / cnt;
            g_invcnt[s] = inv;
            float Ebar = acc[1] * inv;
            float Es = sE[s];
            float Enew = pL + pD * Es * Es + pT * Es * Ebar + pS * E[sC1[s]] * E[sC2[s]];
            g_En[s] = Enew;
            #pragma unroll
            for (int k = 0; k < 8; k++) g_sums[k * SS + s] = acc[2 + k];
        }
    }

    // ---- grid barrier 1: all row-phase outputs visible ----
    grid_barrier(&g_bar1);

    // ---- epilogue: block b handles s = b*8 .. b*8+7, warp-per-s, k-parallel lanes ----
    {
        const unsigned char* lb = (const unsigned char*)is_leaf;
        const unsigned int*  lw = (const unsigned int*)is_leaf;
        const bool leaf = (lb[root] != 0) || (lw[root] == 0x3F800000u);

        float lin;
        if (leaf) {
            lin = (lane == 0) ? g_P[8 * SS + s] : 0.0f;
        } else {
            const int k = lane & 3;          // lanes replicate over 4-lane groups
            const int i1 = sC1[s], i2 = sC2[s];
            const float inv = g_invcnt[s];
            const float q = expf(log_q[root * KK + k]);

            const float* PA = g_P + k * SS;
            const float* PB = g_P + (4 + k) * SS;
            float A  = PA[s],  B  = PB[s];
            float Af = PA[i1], Ag = PA[i2];
            float Bf = PB[i1], Bg = PB[i2];
            float sA = g_sums[k * SS + s];
            float sB = g_sums[(4 + k) * SS + s];

            float part = pS * (q * (Af * Bg + Ag * Bf))
                       + pD * (q * (A * B))
                       + (pT * inv) * (q * (A * sB + B * sA));
            part += __shfl_xor_sync(0xffffffffu, part, 1);
            part += __shfl_xor_sync(0xffffffffu, part, 2);
            if (lane == 0) {
                float sl = g_P[8 * SS + i1] * g_En[i2] + g_P[8 * SS + i2] * g_En[i1];
                part += pS * sl;
            }
            lin = (lane == 0) ? part : 0.0f;
        }
        if (lane == 0) s_part[warp] = lin;
        __syncthreads();
        if (tid == 0) {
            float t = 0.0f;
            #pragma unroll
            for (int w2 = 0; w2 < 8; w2++) t += s_part[w2];
            g_ps[b] = t;
        }
    }

    // ---- grid barrier 2: partials visible ----
    grid_barrier(&g_bar2);

    // ---- block 0 final reduction: 128 partials, one log ----
    if (b == 0 && warp == 0) {
        float v = g_ps[lane] + g_ps[lane + 32] + g_ps[lane + 64] + g_ps[lane + 96];
        #pragma unroll
        for (int o = 16; o > 0; o >>= 1)
            v += __shfl_xor_sync(0xffffffffu, v, o);
        if (lane == 0) out[0] = logf(v);
    }
}

// ---------------- launch ----------------
extern "C" void kernel_launch(void* const* d_in, const int* in_sizes, int n_in,
                              void* d_out, int out_size)
{
    const float* log_delta  = (const float*)d_in[0];
    const float* log_tau    = (const float*)d_in[1];
    const float* log_lambda = (const float*)d_in[2];
    const float* E          = (const float*)d_in[3];
    const float* log_Pi     = (const float*)d_in[4];
    const int*   s_C1       = (const int*)  d_in[5];
    const int*   s_C2       = (const int*)  d_in[6];
    const float* recip      = (const float*)d_in[7];
    const int*   splits_c1  = (const int*)  d_in[8];
    const int*   splits_c2  = (const int*)  d_in[9];
    const float* log_q      = (const float*)d_in[10];
    const void*  is_leaf    = (const void*) d_in[11];
    const int*   root_id    = (const int*)  d_in[12];
    float* out = (float*)d_out;

    k_fused<<<NB, 256>>>(log_delta, log_tau, log_lambda, E, log_Pi,
                         s_C1, s_C2, recip, splits_c1, splits_c2,
                         log_q, is_leaf, root_id, out);
}

// round 9
// speedup vs baseline: 1.1247x; 1.1247x over previous
#include <cuda_runtime.h>
#include <math.h>

#define SS 1024
#define CC 4096
#define KK 4
#define NB 128          // blocks (NB * 8 warps == SS rows); NB <= SM count -> co-resident

// ---------------- scratch (no allocations allowed) ----------------
__device__ float g_sums[8 * SS];   // linear dots  sum_j exp(logPi[c_k][j]) * recip[s][j]
__device__ float g_P[9 * SS];      // exp(logPi) rows: 0..3 = c1 splits, 4..7 = c2 splits, 8 = root
__device__ float g_invcnt[SS];     // 1 / cnt[s]
__device__ float g_En[SS];         // E_new[s]  (linear)
__device__ float g_ps[NB];         // per-block partial sums of lin[s]
__device__ unsigned int g_bar1 = 0, g_bar2 = 0;   // monotonic ticket counters (never reset)

__device__ __forceinline__ float softplusf(float x) {
    if (x > 20.0f)  return x;
    if (x < -20.0f) return expf(x);
    return log1pf(expf(x));            // accurate: used only for 3 uniform scalars
}

// Grid barrier: monotonic counter, replay-safe (no reset), wrap-safe compare.
// All NB blocks are co-resident (NB <= 148 SMs), so spin cannot deadlock.
__device__ __forceinline__ void grid_barrier(unsigned int* bar) {
    __threadfence();                       // release
    __syncthreads();
    if (threadIdx.x == 0) {
        unsigned int t = atomicAdd(bar, 1u);
        unsigned int target = (t / NB + 1u) * NB;
        while ((int)(*(volatile unsigned int*)bar - target) < 0) { }
    }
    __syncthreads();
    __threadfence();                       // acquire
}

__global__ void __launch_bounds__(256) k_fused(
    const float* __restrict__ log_delta,
    const float* __restrict__ log_tau,
    const float* __restrict__ log_lambda,
    const float* __restrict__ E,
    const float* __restrict__ logPi,
    const int*   __restrict__ sC1,
    const int*   __restrict__ sC2,
    const float* __restrict__ recip,
    const int*   __restrict__ splits_c1,
    const int*   __restrict__ splits_c2,
    const float* __restrict__ log_q,
    const void*  __restrict__ is_leaf,
    const int*   __restrict__ rootp,
    float*       __restrict__ out)
{
    __shared__ float sw[8 * SS];   // exp(logPi[c_k][j])  (32 KB)
    __shared__ float sE[SS];       // E (4 KB)
    __shared__ float s_part[8];    // per-warp epilogue partials

    const int tid  = threadIdx.x;
    const int b    = blockIdx.x;
    const int warp = tid >> 5, lane = tid & 31;

    // ---- issue ALL recip loads first (8 outstanding LDG.128 per warp);
    //      their DRAM latency overlaps the staging below.
    const int s = b * 8 + warp;
    const float4* rrow = (const float4*)(recip + (size_t)s * SS);
    float4 rv[8];
    #pragma unroll
    for (int it = 0; it < 8; it++) rv[it] = rrow[lane + it * 32];

    // ---- scalar constants (uniform, L2-hot broadcasts) ----
    const int root = rootp[0];
    const float delta = softplusf(log_delta[0]);
    const float tau   = softplusf(log_tau[0]);
    const float lam   = softplusf(log_lambda[0]);
    const float rs = 1.0f + delta + tau + lam;
    const float pS = 1.0f / rs, pD = delta / rs, pT = tau / rs, pL = lam / rs;

    // ---- stage weights + E in shared (fast exp: args in (-8, 3), __expf rel-err ~2^-22) ----
    #pragma unroll
    for (int k = 0; k < 8; k++) {
        int c = (k < 4) ? splits_c1[root * KK + k] : splits_c2[root * KK + (k - 4)];
        float4 v = ((const float4*)(logPi + (size_t)c * SS))[tid];
        float4 w;
        w.x = __expf(v.x); w.y = __expf(v.y); w.z = __expf(v.z); w.w = __expf(v.w);
        ((float4*)(sw + k * SS))[tid] = w;
    }
    ((float4*)sE)[tid] = ((const float4*)E)[tid];

    // blocks 0..7 publish exp'd split rows; block 8 publishes exp'd root row
    if (b < 8) {
        float4 w = ((const float4*)(sw + b * SS))[tid];   // own thread's write
        ((float4*)(g_P + b * SS))[tid] = w;
    } else if (b == 8) {
        float4 v = ((const float4*)(logPi + (size_t)root * SS))[tid];
        float4 w;
        w.x = __expf(v.x); w.y = __expf(v.y); w.z = __expf(v.z); w.w = __expf(v.w);
        ((float4*)(g_P + 8 * SS))[tid] = w;
    }
    __syncthreads();

    // ---- row phase compute: all rv already in registers ----
    {
        float acc[10];
        #pragma unroll
        for (int q = 0; q < 10; q++) acc[q] = 0.0f;

        #pragma unroll
        for (int it = 0; it < 8; it++) {
            const int j4 = lane + it * 32;
            const float4 r = rv[it];
            const float4 ev = ((const float4*)sE)[j4];
            acc[0] += r.x + r.y + r.z + r.w;
            acc[1] += r.x * ev.x + r.y * ev.y + r.z * ev.z + r.w * ev.w;
            #pragma unroll
            for (int k = 0; k < 8; k++) {
                const float4 wv = ((const float4*)(sw + k * SS))[j4];
                acc[2 + k] += r.x * wv.x + r.y * wv.y + r.z * wv.z + r.w * wv.w;
            }
        }

        #pragma unroll
        for (int q = 0; q < 10; q++)
            #pragma unroll
            for (int o = 16; o > 0; o >>= 1)
                acc[q] += __shfl_xor_sync(0xffffffffu, acc[q], o);

        if (lane == 0) {
            float cnt = fmaxf(acc[0], 1.0f);
            float inv = 1.0f / cnt;
            g_invcnt[s] = inv;
            float Ebar = acc[1] * inv;
            float Es = sE[s];
            float Enew = pL + pD * Es * Es + pT * Es * Ebar + pS * E[sC1[s]] * E[sC2[s]];
            g_En[s] = Enew;
            #pragma unroll
            for (int k = 0; k < 8; k++) g_sums[k * SS + s] = acc[2 + k];
        }
    }

    // ---- grid barrier 1: all row-phase outputs visible ----
    grid_barrier(&g_bar1);

    // ---- epilogue: block b handles s = b*8 .. b*8+7, warp-per-s, k-parallel lanes ----
    {
        const unsigned char* lb = (const unsigned char*)is_leaf;
        const unsigned int*  lw = (const unsigned int*)is_leaf;
        const bool leaf = (lb[root] != 0) || (lw[root] == 0x3F800000u);

        float lin;
        if (leaf) {
            lin = (lane == 0) ? g_P[8 * SS + s] : 0.0f;
        } else {
            const int k = lane & 3;          // lanes replicate over 4-lane groups
            const int i1 = sC1[s], i2 = sC2[s];
            const float inv = g_invcnt[s];
            const float q = __expf(log_q[root * KK + k]);

            const float* PA = g_P + k * SS;
            const float* PB = g_P + (4 + k) * SS;
            float A  = PA[s],  B  = PB[s];
            float Af = PA[i1], Ag = PA[i2];
            float Bf = PB[i1], Bg = PB[i2];
            float sA = g_sums[k * SS + s];
            float sB = g_sums[(4 + k) * SS + s];

            float part = pS * (q * (Af * Bg + Ag * Bf))
                       + pD * (q * (A * B))
                       + (pT * inv) * (q * (A * sB + B * sA));
            part += __shfl_xor_sync(0xffffffffu, part, 1);
            part += __shfl_xor_sync(0xffffffffu, part, 2);
            if (lane == 0) {
                float sl = g_P[8 * SS + i1] * g_En[i2] + g_P[8 * SS + i2] * g_En[i1];
                part += pS * sl;
            }
            lin = (lane == 0) ? part : 0.0f;
        }
        if (lane == 0) s_part[warp] = lin;
        __syncthreads();
        if (tid == 0) {
            float t = 0.0f;
            #pragma unroll
            for (int w2 = 0; w2 < 8; w2++) t += s_part[w2];
            g_ps[b] = t;
        }
    }

    // ---- grid barrier 2: partials visible ----
    grid_barrier(&g_bar2);

    // ---- block 0 final reduction: 128 partials, one log ----
    if (b == 0 && warp == 0) {
        float v = g_ps[lane] + g_ps[lane + 32] + g_ps[lane + 64] + g_ps[lane + 96];
        #pragma unroll
        for (int o = 16; o > 0; o >>= 1)
            v += __shfl_xor_sync(0xffffffffu, v, o);
        if (lane == 0) out[0] = logf(v);   // one accurate log
    }
}

// ---------------- launch ----------------
extern "C" void kernel_launch(void* const* d_in, const int* in_sizes, int n_in,
                              void* d_out, int out_size)
{
    const float* log_delta  = (const float*)d_in[0];
    const float* log_tau    = (const float*)d_in[1];
    const float* log_lambda = (const float*)d_in[2];
    const float* E          = (const float*)d_in[3];
    const float* log_Pi     = (const float*)d_in[4];
    const int*   s_C1       = (const int*)  d_in[5];
    const int*   s_C2       = (const int*)  d_in[6];
    const float* recip      = (const float*)d_in[7];
    const int*   splits_c1  = (const int*)  d_in[8];
    const int*   splits_c2  = (const int*)  d_in[9];
    const float* log_q      = (const float*)d_in[10];
    const void*  is_leaf    = (const void*) d_in[11];
    const int*   root_id    = (const int*)  d_in[12];
    float* out = (float*)d_out;

    k_fused<<<NB, 256>>>(log_delta, log_tau, log_lambda, E, log_Pi,
                         s_C1, s_C2, recip, splits_c1, splits_c2,
                         log_q, is_leaf, root_id, out);
}

// round 10
// speedup vs baseline: 1.1500x; 1.0225x over previous
#include <cuda_runtime.h>
#include <math.h>

#define SS 1024
#define CC 4096
#define KK 4
#define NB 128          // blocks (NB * 8 warps == SS rows); NB <= SM count -> co-resident

// ---------------- scratch (no allocations allowed) ----------------
__device__ float g_En[SS];         // E_new[s]  (linear) — the ONLY cross-block array
__device__ float g_ps[NB];         // per-block partial sums of lin[s]
__device__ unsigned int g_bar1 = 0;        // grid barrier ticket (monotonic)
__device__ unsigned int g_done = 0;        // last-block ticket (monotonic)

__device__ __forceinline__ float softplusf(float x) {
    if (x > 20.0f)  return x;
    if (x < -20.0f) return expf(x);
    return log1pf(expf(x));            // accurate: only 3 uniform scalars
}

// Grid barrier: monotonic counter, replay-safe (no reset), wrap-safe compare.
__device__ __forceinline__ void grid_barrier(unsigned int* bar) {
    __threadfence();                       // release
    __syncthreads();
    if (threadIdx.x == 0) {
        unsigned int t = atomicAdd(bar, 1u);
        unsigned int target = (t / NB + 1u) * NB;
        while ((int)(*(volatile unsigned int*)bar - target) < 0) { }
    }
    __syncthreads();
    __threadfence();                       // acquire
}

__global__ void __launch_bounds__(256) k_fused(
    const float* __restrict__ log_delta,
    const float* __restrict__ log_tau,
    const float* __restrict__ log_lambda,
    const float* __restrict__ E,
    const float* __restrict__ logPi,
    const int*   __restrict__ sC1,
    const int*   __restrict__ sC2,
    const float* __restrict__ recip,
    const int*   __restrict__ splits_c1,
    const int*   __restrict__ splits_c2,
    const float* __restrict__ log_q,
    const void*  __restrict__ is_leaf,
    const int*   __restrict__ rootp,
    float*       __restrict__ out)
{
    __shared__ float sw[9 * SS];   // exp(logPi) rows: 0..3 c1, 4..7 c2, 8 root  (36 KB)
    __shared__ float sE[SS];       // E (4 KB)
    __shared__ float s_part[8];    // per-warp partials
    __shared__ unsigned int s_islast;

    const int tid  = threadIdx.x;
    const int b    = blockIdx.x;
    const int warp = tid >> 5, lane = tid & 31;
    const int s    = b * 8 + warp;

    // ---- issue independent DRAM loads first: recip row (8 LDG.128/warp) + i1/i2 ----
    const float4* rrow = (const float4*)(recip + (size_t)s * SS);
    float4 rv[8];
    #pragma unroll
    for (int it = 0; it < 8; it++) rv[it] = rrow[lane + it * 32];
    const int i1 = sC1[s], i2 = sC2[s];

    // ---- scalar constants (uniform broadcasts) ----
    const int root = rootp[0];
    const float delta = softplusf(log_delta[0]);
    const float tau   = softplusf(log_tau[0]);
    const float lam   = softplusf(log_lambda[0]);
    const float rs = 1.0f + delta + tau + lam;
    const float pS = 1.0f / rs, pD = delta / rs, pT = tau / rs, pL = lam / rs;

    const unsigned char* lbp = (const unsigned char*)is_leaf;
    const unsigned int*  lwp = (const unsigned int*)is_leaf;
    const bool leaf = (lbp[root] != 0) || (lwp[root] == 0x3F800000u);

    // ---- stage 9 exp'd rows + E in shared ----
    #pragma unroll
    for (int k = 0; k < 9; k++) {
        int c = (k < 4) ? splits_c1[root * KK + k]
              : (k < 8) ? splits_c2[root * KK + (k - 4)]
                        : root;
        float4 v = ((const float4*)(logPi + (size_t)c * SS))[tid];
        float4 w;
        w.x = __expf(v.x); w.y = __expf(v.y); w.z = __expf(v.z); w.w = __expf(v.w);
        ((float4*)(sw + k * SS))[tid] = w;
    }
    ((float4*)sE)[tid] = ((const float4*)E)[tid];
    __syncthreads();

    // ---- row dots: warp-per-row, rv already in registers ----
    float acc[10];
    #pragma unroll
    for (int q = 0; q < 10; q++) acc[q] = 0.0f;

    #pragma unroll
    for (int it = 0; it < 8; it++) {
        const int j4 = lane + it * 32;
        const float4 r = rv[it];
        const float4 ev = ((const float4*)sE)[j4];
        acc[0] += r.x + r.y + r.z + r.w;
        acc[1] += r.x * ev.x + r.y * ev.y + r.z * ev.z + r.w * ev.w;
        #pragma unroll
        for (int k = 0; k < 8; k++) {
            const float4 wv = ((const float4*)(sw + k * SS))[j4];
            acc[2 + k] += r.x * wv.x + r.y * wv.y + r.z * wv.z + r.w * wv.w;
        }
    }
    #pragma unroll
    for (int q = 0; q < 10; q++)
        #pragma unroll
        for (int o = 16; o > 0; o >>= 1)
            acc[q] += __shfl_xor_sync(0xffffffffu, acc[q], o);   // totals in ALL lanes

    const float cnt = fmaxf(acc[0], 1.0f);
    const float inv = 1.0f / cnt;

    // ---- local epilogue (pre-barrier): lanes 0..3 handle k, all data in smem/regs ----
    float lin_local = 0.0f;
    if (!leaf) {
        if (lane < 4) {
            const int k = lane;
            const float q = __expf(log_q[root * KK + k]);
            const float* PA = sw + k * SS;
            const float* PB = sw + (4 + k) * SS;
            float A  = PA[s],  B  = PB[s];
            float Af = PA[i1], Ag = PA[i2];
            float Bf = PB[i1], Bg = PB[i2];
            float sA = acc[2 + k];      // dot(w_c1k, recip[s])
            float sB = acc[6 + k];      // dot(w_c2k, recip[s])
            lin_local = q * (pS * (Af * Bg + Ag * Bf)
                           + pD * (A * B)
                           + (pT * inv) * (A * sB + B * sA));
        }
        lin_local += __shfl_xor_sync(0xffffffffu, lin_local, 1);
        lin_local += __shfl_xor_sync(0xffffffffu, lin_local, 2);  // sum of 4 k-terms on lane 0
    }

    // ---- publish E_new[s] (the only cross-block value) ----
    if (lane == 0) {
        float Ebar = acc[1] * inv;
        float Es = sE[s];
        float Enew = pL + pD * Es * Es + pT * Es * Ebar + pS * sE[i1] * sE[i2];
        g_En[s] = Enew;
    }

    // ---- grid barrier: all g_En visible ----
    grid_barrier(&g_bar1);

    // ---- sl term + per-block sum ----
    if (lane == 0) {
        float lin;
        if (leaf) {
            lin = sw[8 * SS + s];
        } else {
            float sl = sw[8 * SS + i1] * g_En[i2] + sw[8 * SS + i2] * g_En[i1];
            lin = lin_local + pS * sl;
        }
        s_part[warp] = lin;
    }
    __syncthreads();
    if (tid == 0) {
        float t = 0.0f;
        #pragma unroll
        for (int w2 = 0; w2 < 8; w2++) t += s_part[w2];
        g_ps[b] = t;
        __threadfence();
        unsigned int prev = atomicAdd(&g_done, 1u);
        s_islast = ((prev % NB) == (unsigned int)(NB - 1)) ? 1u : 0u;
    }
    __syncthreads();
    if (!s_islast) return;
    __threadfence();   // acquire: all partials visible

    // ---- last block: fixed-order deterministic final sum + one log ----
    if (warp == 0) {
        float v = g_ps[lane] + g_ps[lane + 32] + g_ps[lane + 64] + g_ps[lane + 96];
        #pragma unroll
        for (int o = 16; o > 0; o >>= 1)
            v += __shfl_xor_sync(0xffffffffu, v, o);
        if (lane == 0) out[0] = logf(v);
    }
}

// ---------------- launch ----------------
extern "C" void kernel_launch(void* const* d_in, const int* in_sizes, int n_in,
                              void* d_out, int out_size)
{
    const float* log_delta  = (const float*)d_in[0];
    const float* log_tau    = (const float*)d_in[1];
    const float* log_lambda = (const float*)d_in[2];
    const float* E          = (const float*)d_in[3];
    const float* log_Pi     = (const float*)d_in[4];
    const int*   s_C1       = (const int*)  d_in[5];
    const int*   s_C2       = (const int*)  d_in[6];
    const float* recip      = (const float*)d_in[7];
    const int*   splits_c1  = (const int*)  d_in[8];
    const int*   splits_c2  = (const int*)  d_in[9];
    const float* log_q      = (const float*)d_in[10];
    const void*  is_leaf    = (const void*) d_in[11];
    const int*   root_id    = (const int*)  d_in[12];
    float* out = (float*)d_out;

    k_fused<<<NB, 256>>>(log_delta, log_tau, log_lambda, E, log_Pi,
                         s_C1, s_C2, recip, splits_c1, splits_c2,
                         log_q, is_leaf, root_id, out);
}